// round 2
// baseline (speedup 1.0000x reference)
#include <cuda_runtime.h>
#include <cstddef>
#include <cstdint>

#define B_N 4096
#define HID 256
#define OBS_D 400
#define IN_D 432

// ---------------- scratch (device globals; no allocation allowed) ----------------
// state order: h0,c0, h1,c1, h1b,c1b, h2,c2, h2b,c2b, h3b,c3b, h4b,c4b
__device__ float g_state[14 * B_N * HID];
__device__ float g_samp[4 * B_N * 16];      // prev_pid, samp_sid, samp_sid0, samp_sid1
__device__ float g_obs_emb[B_N * OBS_D];
__device__ float g_xpre[B_N * 1024];
__device__ float g_WhhT[256 * 1024];
__device__ float g_W0T[400 * 1024];
__device__ float g_WextT[32 * 1024];        // rows 0..15: samp cols of W_ih; 16..31: addr cols
__device__ float g_bias[1024];              // b_ih + b_hh
__device__ float g_rp0[B_N * 2];
__device__ float g_z1[B_N * 100];
__device__ float g_z2[B_N * 100];
__device__ float g_rp0emb[B_N * 16];

__device__ __forceinline__ float sigf(float x) { return 1.f / (1.f + __expf(-x)); }
__device__ __forceinline__ float tanh_fast(float x) { return 2.f / (1.f + __expf(-2.f * x)) - 1.f; }

#define FMA4(A_, s_, W_) { (A_).x += (s_)*(W_).x; (A_).y += (s_)*(W_).y; (A_).z += (s_)*(W_).z; (A_).w += (s_)*(W_).w; }

// ---------------- weight prep: transposes for coalesced GEMM loads ----------------
__global__ void prep_weights_kernel(const float* __restrict__ W_ih, const float* __restrict__ b_ih,
                                    const float* __restrict__ W_hh, const float* __restrict__ b_hh,
                                    float* __restrict__ WhhT, float* __restrict__ W0T,
                                    float* __restrict__ WextT, float* __restrict__ bias) {
    int idx = blockIdx.x * blockDim.x + threadIdx.x;
    int stride = gridDim.x * blockDim.x;
    for (int i = idx; i < 256 * 1024; i += stride) { int k = i >> 10, j = i & 1023; WhhT[i] = W_hh[(size_t)j * 256 + k]; }
    for (int i = idx; i < 400 * 1024; i += stride) { int k = i >> 10, j = i & 1023; W0T[i] = W_ih[(size_t)j * IN_D + k]; }
    for (int i = idx; i < 32 * 1024;  i += stride) { int k = i >> 10, j = i & 1023; WextT[i] = W_ih[(size_t)j * IN_D + 400 + k]; }
    for (int i = idx; i < 1024; i += stride) bias[i] = b_ih[i] + b_hh[i];
}

// ---------------- embedding gathers ----------------
__global__ void gather_kernel(const int* __restrict__ pid, const int* __restrict__ sid,
                              const int* __restrict__ sid0, const int* __restrict__ sid1,
                              const float* __restrict__ pid_emb, const float* __restrict__ sid_emb,
                              float* __restrict__ s_pid, float* __restrict__ s_sid,
                              float* __restrict__ s_sid0, float* __restrict__ s_sid1) {
    int i = blockIdx.x * blockDim.x + threadIdx.x;
    if (i >= B_N * 16) return;
    int b = i >> 4, k = i & 15;
    s_pid[i]  = pid_emb[pid[b]  * 16 + k];
    s_sid[i]  = sid_emb[sid[b]  * 16 + k];
    s_sid0[i] = sid_emb[sid0[b] * 16 + k];
    s_sid1[i] = sid_emb[sid1[b] * 16 + k];
}

// ---------------- fused conv1+conv2+pool (one block per sample) ----------------
__global__ void __launch_bounds__(256) conv_fused_kernel(
    const float* __restrict__ obs, const float* __restrict__ w1, const float* __restrict__ b1,
    const float* __restrict__ w2, const float* __restrict__ b2, float* __restrict__ obs_emb) {
    extern __shared__ float sm[];
    float* s_in = sm;              // 4096
    float* s_w1 = s_in + 4096;     // 288
    float* s_b1 = s_w1 + 288;      // 32
    float* s_w2 = s_b1 + 32;       // 4608
    float* s_b2 = s_w2 + 4608;     // 16
    float* s_c1 = s_b2 + 16;       // 32768
    float* s_c2 = s_c1 + 32768;    // 4096
    int tid = threadIdx.x;
    int b = blockIdx.x;
    const float* in = obs + (size_t)b * 4096;
    for (int i = tid; i < 1024; i += 256) ((float4*)s_in)[i] = ((const float4*)in)[i];
    for (int i = tid; i < 288; i += 256) s_w1[i] = w1[i];
    for (int i = tid; i < 32; i += 256) s_b1[i] = b1[i];
    for (int i = tid; i < 4608; i += 256) s_w2[i] = w2[i];
    for (int i = tid; i < 16; i += 256) s_b2[i] = b2[i];
    __syncthreads();
    // conv1: (1,64,64) -> (32,32,32), stride 2, pad 1, relu
    for (int o = tid; o < 32768; o += 256) {
        int oc = o >> 10;
        int oy = (o >> 5) & 31;
        int ox = o & 31;
        const float* w = s_w1 + oc * 9;
        float acc = s_b1[oc];
        int iy0 = oy * 2 - 1, ix0 = ox * 2 - 1;
        #pragma unroll
        for (int dy = 0; dy < 3; dy++) {
            int iy = iy0 + dy;
            if ((unsigned)iy < 64u) {
                #pragma unroll
                for (int dx = 0; dx < 3; dx++) {
                    int ix = ix0 + dx;
                    if ((unsigned)ix < 64u) acc += w[dy * 3 + dx] * s_in[iy * 64 + ix];
                }
            }
        }
        s_c1[o] = fmaxf(acc, 0.f);
    }
    __syncthreads();
    // conv2: (32,32,32) -> (16,16,16), stride 2, pad 1, relu. Tile: 4oc x 2x2 spatial.
    {
        int ocg = tid >> 6;               // 0..3 -> oc base 4*ocg
        int oy0 = ((tid >> 3) & 7) * 2;   // 0,2,..,14
        int ox0 = (tid & 7) * 2;
        float acc[4][2][2];
        #pragma unroll
        for (int a = 0; a < 4; a++)
            #pragma unroll
            for (int sy = 0; sy < 2; sy++)
                #pragma unroll
                for (int sx = 0; sx < 2; sx++) acc[a][sy][sx] = 0.f;
        int iy0 = oy0 * 2 - 1, ix0 = ox0 * 2 - 1;
        for (int ic = 0; ic < 32; ic++) {
            float inp[5][5];
            #pragma unroll
            for (int r = 0; r < 5; r++) {
                int iy = iy0 + r;
                bool okr = (unsigned)iy < 32u;
                #pragma unroll
                for (int cc = 0; cc < 5; cc++) {
                    int ix = ix0 + cc;
                    inp[r][cc] = (okr && (unsigned)ix < 32u) ? s_c1[ic * 1024 + iy * 32 + ix] : 0.f;
                }
            }
            #pragma unroll
            for (int o4 = 0; o4 < 4; o4++) {
                const float* w = s_w2 + ((ocg * 4 + o4) * 32 + ic) * 9;
                float wv[9];
                #pragma unroll
                for (int q = 0; q < 9; q++) wv[q] = w[q];
                #pragma unroll
                for (int sy = 0; sy < 2; sy++)
                    #pragma unroll
                    for (int sx = 0; sx < 2; sx++)
                        #pragma unroll
                        for (int dy = 0; dy < 3; dy++)
                            #pragma unroll
                            for (int dx = 0; dx < 3; dx++)
                                acc[o4][sy][sx] += wv[dy * 3 + dx] * inp[sy * 2 + dy][sx * 2 + dx];
            }
        }
        #pragma unroll
        for (int o4 = 0; o4 < 4; o4++) {
            float bb = s_b2[ocg * 4 + o4];
            #pragma unroll
            for (int sy = 0; sy < 2; sy++)
                #pragma unroll
                for (int sx = 0; sx < 2; sx++)
                    s_c2[(ocg * 4 + o4) * 256 + (oy0 + sy) * 16 + (ox0 + sx)] = fmaxf(acc[o4][sy][sx] + bb, 0.f);
        }
    }
    __syncthreads();
    // avg pool 3x3 stride 3 VALID -> (16,5,5) -> 400
    for (int o = tid; o < 400; o += 256) {
        int c = o / 25;
        int rem = o - c * 25;
        int py = rem / 5, px = rem - (rem / 5) * 5;
        float s = 0.f;
        #pragma unroll
        for (int dy = 0; dy < 3; dy++)
            #pragma unroll
            for (int dx = 0; dx < 3; dx++)
                s += s_c2[c * 256 + (py * 3 + dy) * 16 + (px * 3 + dx)];
        obs_emb[(size_t)b * OBS_D + o] = s * (1.f / 9.f);
    }
}

// ---------------- xpre = obs_emb @ W0T + (b_ih+b_hh) : [B,400]x[400,1024] ----------------
__global__ void __launch_bounds__(256) gemm_xpre_kernel(
    const float* __restrict__ A, const float* __restrict__ W0T,
    const float* __restrict__ bias, float* __restrict__ out) {
    __shared__ float As[16 * 64];
    __shared__ float Ws[16 * 128];
    int tid = threadIdx.x;
    int tx = tid & 31, ty = tid >> 5;
    int row0 = blockIdx.y * 64;
    int jb = blockIdx.x * 128;
    int a_r = tid >> 2, a_k = (tid & 3) * 4;
    float4 acc[8];
    #pragma unroll
    for (int r = 0; r < 8; r++) acc[r] = make_float4(0.f, 0.f, 0.f, 0.f);
    for (int k0 = 0; k0 < 400; k0 += 16) {
        float4 av = *(const float4*)&A[(size_t)(row0 + a_r) * OBS_D + k0 + a_k];
        As[(a_k + 0) * 64 + a_r] = av.x;
        As[(a_k + 1) * 64 + a_r] = av.y;
        As[(a_k + 2) * 64 + a_r] = av.z;
        As[(a_k + 3) * 64 + a_r] = av.w;
        #pragma unroll
        for (int q = 0; q < 2; q++) {
            int idx = tid + 256 * q;
            int kk = idx >> 5, c4 = (idx & 31) * 4;
            *(float4*)&Ws[kk * 128 + c4] = *(const float4*)&W0T[(size_t)(k0 + kk) * 1024 + jb + c4];
        }
        __syncthreads();
        #pragma unroll
        for (int kk = 0; kk < 16; kk++) {
            float4 w = *(float4*)&Ws[kk * 128 + tx * 4];
            float4 a0 = *(float4*)&As[kk * 64 + ty * 8];
            float4 a1 = *(float4*)&As[kk * 64 + ty * 8 + 4];
            FMA4(acc[0], a0.x, w); FMA4(acc[1], a0.y, w); FMA4(acc[2], a0.z, w); FMA4(acc[3], a0.w, w);
            FMA4(acc[4], a1.x, w); FMA4(acc[5], a1.y, w); FMA4(acc[6], a1.z, w); FMA4(acc[7], a1.w, w);
        }
        __syncthreads();
    }
    float4 bv = *(const float4*)&bias[jb + tx * 4];
    #pragma unroll
    for (int r = 0; r < 8; r++) {
        size_t b = row0 + ty * 8 + r;
        float4 o = acc[r];
        o.x += bv.x; o.y += bv.y; o.z += bv.z; o.w += bv.w;
        *(float4*)&out[b * 1024 + jb + tx * 4] = o;
    }
}

// ---------------- LSTM step: GEMM over h (K=256) + samp/addr K-extension + fused gates ----------------
#define STEP_TILE() \
    __syncthreads(); \
    _Pragma("unroll") \
    for (int kk = 0; kk < 16; kk++) { \
        float4 a = *(float4*)&As[kk * 64 + ty4]; \
        _Pragma("unroll") \
        for (int gt = 0; gt < 4; gt++) { \
            float4 w = *(float4*)&Ws[(gt * 16 + kk) * 64 + tx4]; \
            FMA4(acc[gt][0], a.x, w); \
            FMA4(acc[gt][1], a.y, w); \
            FMA4(acc[gt][2], a.z, w); \
            FMA4(acc[gt][3], a.w, w); \
        } \
    } \
    __syncthreads();

__global__ void __launch_bounds__(256) lstm_step_kernel(
    const float* __restrict__ xpre,
    const float* __restrict__ h_in, const float* __restrict__ c_in,
    const float* __restrict__ samp,
    const float* __restrict__ WhhT, const float* __restrict__ WextT,
    const float* __restrict__ addr_emb, int aid,
    float* __restrict__ h_out, float* __restrict__ c_out) {
    __shared__ float As[16 * 64];
    __shared__ float Ws[4 * 16 * 64];
    const int tid = threadIdx.x;
    const int tx4 = (tid & 15) * 4;
    const int ty4 = (tid >> 4) * 4;
    const int row0 = blockIdx.y * 64;
    const int j0 = blockIdx.x * 64;
    const int a_r = tid >> 2;
    const int a_k = (tid & 3) * 4;
    float4 acc[4][4];
    #pragma unroll
    for (int gt = 0; gt < 4; gt++)
        #pragma unroll
        for (int r = 0; r < 4; r++) acc[gt][r] = make_float4(0.f, 0.f, 0.f, 0.f);

    if (h_in) {
        for (int k0 = 0; k0 < 256; k0 += 16) {
            float4 av = *(const float4*)&h_in[(size_t)(row0 + a_r) * 256 + k0 + a_k];
            As[(a_k + 0) * 64 + a_r] = av.x;
            As[(a_k + 1) * 64 + a_r] = av.y;
            As[(a_k + 2) * 64 + a_r] = av.z;
            As[(a_k + 3) * 64 + a_r] = av.w;
            #pragma unroll
            for (int q = 0; q < 4; q++) {
                int idx = tid + 256 * q;
                int kk = (idx >> 4) & 15;
                int gt = idx >> 8;
                int c4 = (idx & 15) * 4;
                *(float4*)&Ws[(idx >> 4) * 64 + c4] = *(const float4*)&WhhT[(size_t)(k0 + kk) * 1024 + gt * 256 + j0 + c4];
            }
            STEP_TILE()
        }
    }
    if (samp) {
        float4 av = *(const float4*)&samp[(size_t)(row0 + a_r) * 16 + a_k];
        As[(a_k + 0) * 64 + a_r] = av.x;
        As[(a_k + 1) * 64 + a_r] = av.y;
        As[(a_k + 2) * 64 + a_r] = av.z;
        As[(a_k + 3) * 64 + a_r] = av.w;
        #pragma unroll
        for (int q = 0; q < 4; q++) {
            int idx = tid + 256 * q;
            int kk = (idx >> 4) & 15;
            int gt = idx >> 8;
            int c4 = (idx & 15) * 4;
            *(float4*)&Ws[(idx >> 4) * 64 + c4] = *(const float4*)&WextT[(size_t)kk * 1024 + gt * 256 + j0 + c4];
        }
        STEP_TILE()
    }
    {
        float4 av = *(const float4*)&addr_emb[aid * 16 + a_k];
        As[(a_k + 0) * 64 + a_r] = av.x;
        As[(a_k + 1) * 64 + a_r] = av.y;
        As[(a_k + 2) * 64 + a_r] = av.z;
        As[(a_k + 3) * 64 + a_r] = av.w;
        #pragma unroll
        for (int q = 0; q < 4; q++) {
            int idx = tid + 256 * q;
            int kk = (idx >> 4) & 15;
            int gt = idx >> 8;
            int c4 = (idx & 15) * 4;
            *(float4*)&Ws[(idx >> 4) * 64 + c4] = *(const float4*)&WextT[(size_t)(16 + kk) * 1024 + gt * 256 + j0 + c4];
        }
        STEP_TILE()
    }
    // fused gate epilogue
    #pragma unroll
    for (int r = 0; r < 4; r++) {
        size_t b = row0 + ty4 + r;
        float4 xi = *(const float4*)&xpre[b * 1024 + 0   + j0 + tx4];
        float4 xf = *(const float4*)&xpre[b * 1024 + 256 + j0 + tx4];
        float4 xg = *(const float4*)&xpre[b * 1024 + 512 + j0 + tx4];
        float4 xo = *(const float4*)&xpre[b * 1024 + 768 + j0 + tx4];
        float4 cold = make_float4(0.f, 0.f, 0.f, 0.f);
        if (c_in) cold = *(const float4*)&c_in[b * 256 + j0 + tx4];
        float4 hv, cv;
        #define GATE(comp) { \
            float iv = acc[0][r].comp + xi.comp; \
            float fv = acc[1][r].comp + xf.comp; \
            float gv = acc[2][r].comp + xg.comp; \
            float ov = acc[3][r].comp + xo.comp; \
            float cn = sigf(fv) * cold.comp + sigf(iv) * tanh_fast(gv); \
            cv.comp = cn; \
            hv.comp = sigf(ov) * tanh_fast(cn); }
        GATE(x) GATE(y) GATE(z) GATE(w)
        #undef GATE
        *(float4*)&h_out[b * 256 + j0 + tx4] = hv;
        *(float4*)&c_out[b * 256 + j0 + tx4] = cv;
    }
}

// ---------------- heads ----------------
__global__ void head_linear_kernel(const float* __restrict__ h, const float* __restrict__ W,
                                   const float* __restrict__ bias, int O, int col0,
                                   float* __restrict__ out) {
    int gw = (blockIdx.x * blockDim.x + threadIdx.x) >> 5;
    int lane = threadIdx.x & 31;
    if (gw >= B_N) return;
    float4 h0 = *(const float4*)&h[(size_t)gw * 256 + lane * 8];
    float4 h1 = *(const float4*)&h[(size_t)gw * 256 + lane * 8 + 4];
    for (int o = 0; o < O; o++) {
        const float* w = W + o * 256 + lane * 8;
        float4 w0 = *(const float4*)w;
        float4 w1 = *(const float4*)(w + 4);
        float s = h0.x * w0.x + h0.y * w0.y + h0.z * w0.z + h0.w * w0.w
                + h1.x * w1.x + h1.y * w1.y + h1.z * w1.z + h1.w * w1.w;
        #pragma unroll
        for (int off = 16; off; off >>= 1) s += __shfl_down_sync(0xffffffffu, s, off);
        if (lane == 0) out[(size_t)gw * 15 + col0 + o] = s + bias[o];
    }
}

__global__ void head_rp_kernel(const float* __restrict__ h, const float* __restrict__ W,
                               const float* __restrict__ bias, const float* __restrict__ eps,
                               int col0, float* __restrict__ out, float* __restrict__ save) {
    int gw = (blockIdx.x * blockDim.x + threadIdx.x) >> 5;
    int lane = threadIdx.x & 31;
    if (gw >= B_N) return;
    float4 h0 = *(const float4*)&h[(size_t)gw * 256 + lane * 8];
    float4 h1 = *(const float4*)&h[(size_t)gw * 256 + lane * 8 + 4];
    float d[4];
    #pragma unroll
    for (int o = 0; o < 4; o++) {
        const float* w = W + o * 256 + lane * 8;
        float4 w0 = *(const float4*)w;
        float4 w1 = *(const float4*)(w + 4);
        float s = h0.x * w0.x + h0.y * w0.y + h0.z * w0.z + h0.w * w0.w
                + h1.x * w1.x + h1.y * w1.y + h1.z * w1.z + h1.w * w1.w;
        #pragma unroll
        for (int off = 16; off; off >>= 1) s += __shfl_down_sync(0xffffffffu, s, off);
        d[o] = s + bias[o];
    }
    if (lane == 0) {
        float r0 = d[0] + __expf(d[2]) * eps[(size_t)gw * 2 + 0];
        float r1 = d[1] + __expf(d[3]) * eps[(size_t)gw * 2 + 1];
        out[(size_t)gw * 15 + col0 + 0] = r0;
        out[(size_t)gw * 15 + col0 + 1] = r1;
        if (save) { save[(size_t)gw * 2 + 0] = r0; save[(size_t)gw * 2 + 1] = r1; }
    }
}

// ---------------- MLP: rp0(2) -> 100 -> 100 -> 16 ----------------
__global__ void mlp1_kernel(const float* __restrict__ rp0, const float* __restrict__ w1,
                            const float* __restrict__ b1, float* __restrict__ z1) {
    int i = blockIdx.x * blockDim.x + threadIdx.x;
    if (i >= B_N * 100) return;
    int b = i / 100, j = i - b * 100;
    float v = rp0[b * 2] * w1[j * 2] + rp0[b * 2 + 1] * w1[j * 2 + 1] + b1[j];
    z1[i] = tanh_fast(v);
}

__global__ void __launch_bounds__(128) mlp2_kernel(const float* __restrict__ z1, const float* __restrict__ w2,
                                                   const float* __restrict__ b2, float* __restrict__ z2) {
    __shared__ float w2s[100 * 101];
    __shared__ float z1s[8 * 100];
    __shared__ float b2s[100];
    int tid = threadIdx.x;
    int b0 = blockIdx.x * 8;
    for (int i = tid; i < 100 * 100; i += 128) { int j = i / 100, k = i - j * 100; w2s[j * 101 + k] = w2[i]; }
    for (int i = tid; i < 800; i += 128) z1s[i] = z1[(size_t)b0 * 100 + i];
    for (int i = tid; i < 100; i += 128) b2s[i] = b2[i];
    __syncthreads();
    for (int t = tid; t < 800; t += 128) {
        int r = t / 100, j = t - r * 100;
        float s = b2s[j];
        const float* zz = z1s + r * 100;
        const float* ww = w2s + j * 101;
        #pragma unroll 4
        for (int k = 0; k < 100; k++) s += zz[k] * ww[k];
        z2[(size_t)(b0 + r) * 100 + j] = tanh_fast(s);
    }
}

__global__ void mlp3_kernel(const float* __restrict__ z2, const float* __restrict__ w3,
                            const float* __restrict__ b3, float* __restrict__ remb) {
    int i = blockIdx.x * blockDim.x + threadIdx.x;
    if (i >= B_N * 16) return;
    int b = i >> 4, o = i & 15;
    float s = b3[o];
    const float* zz = z2 + (size_t)b * 100;
    const float* ww = w3 + o * 100;
    #pragma unroll 4
    for (int k = 0; k < 100; k++) s += zz[k] * ww[k];
    remb[i] = s;
}

// ---------------- host ----------------
static float* getsym(const void* symbol) {
    void* p = nullptr;
    cudaGetSymbolAddress(&p, symbol);
    return (float*)p;
}

extern "C" void kernel_launch(void* const* d_in, const int* in_sizes, int n_in,
                              void* d_out, int out_size) {
    const float* obs        = (const float*)d_in[0];
    const int*   program_id = (const int*)  d_in[1];
    const int*   shape_id   = (const int*)  d_in[2];
    const int*   shape_id_0 = (const int*)  d_in[3];
    const int*   shape_id_1 = (const int*)  d_in[4];
    const float* eps_rp     = (const float*)d_in[5];
    const float* eps_rp0    = (const float*)d_in[6];
    const float* eps_rp1    = (const float*)d_in[7];
    const float* conv1_w    = (const float*)d_in[8];
    const float* conv1_b    = (const float*)d_in[9];
    const float* conv2_w    = (const float*)d_in[10];
    const float* conv2_b    = (const float*)d_in[11];
    const float* mlp_w1     = (const float*)d_in[12];
    const float* mlp_b1     = (const float*)d_in[13];
    const float* mlp_w2     = (const float*)d_in[14];
    const float* mlp_b2     = (const float*)d_in[15];
    const float* mlp_w3     = (const float*)d_in[16];
    const float* mlp_b3     = (const float*)d_in[17];
    const float* W_ih       = (const float*)d_in[18];
    const float* b_ih       = (const float*)d_in[19];
    const float* W_hh       = (const float*)d_in[20];
    const float* b_hh       = (const float*)d_in[21];
    const float* addr_emb   = (const float*)d_in[22];
    const float* pid_emb    = (const float*)d_in[23];
    const float* sid_emb    = (const float*)d_in[24];
    const float* pid_ext_w  = (const float*)d_in[25];
    const float* pid_ext_b  = (const float*)d_in[26];
    const float* sid_ext_w  = (const float*)d_in[27];
    const float* sid_ext_b  = (const float*)d_in[28];
    const float* rp_ext_w   = (const float*)d_in[29];
    const float* rp_ext_b   = (const float*)d_in[30];
    float* out = (float*)d_out;

    float* st      = getsym(g_state);
    const int SZ   = B_N * HID;
    float* h0  = st + 0 * SZ;  float* c0  = st + 1 * SZ;
    float* h1  = st + 2 * SZ;  float* c1  = st + 3 * SZ;
    float* h1b = st + 4 * SZ;  float* c1b = st + 5 * SZ;
    float* h2  = st + 6 * SZ;  float* c2  = st + 7 * SZ;
    float* h2b = st + 8 * SZ;  float* c2b = st + 9 * SZ;
    float* h3b = st + 10 * SZ; float* c3b = st + 11 * SZ;
    float* h4b = st + 12 * SZ; float* c4b = st + 13 * SZ;

    float* samp   = getsym(g_samp);
    float* s_pid  = samp + 0 * B_N * 16;
    float* s_sid  = samp + 1 * B_N * 16;
    float* s_sid0 = samp + 2 * B_N * 16;
    float* s_sid1 = samp + 3 * B_N * 16;

    float* obs_e  = getsym(g_obs_emb);
    float* xpre   = getsym(g_xpre);
    float* WhhT   = getsym(g_WhhT);
    float* W0T    = getsym(g_W0T);
    float* WextT  = getsym(g_WextT);
    float* bias   = getsym(g_bias);
    float* rp0    = getsym(g_rp0);
    float* z1     = getsym(g_z1);
    float* z2     = getsym(g_z2);
    float* rp0emb = getsym(g_rp0emb);

    const int CONV_SMEM = (4096 + 288 + 32 + 4608 + 16 + 32768 + 4096) * 4;
    cudaFuncSetAttribute(conv_fused_kernel, cudaFuncAttributeMaxDynamicSharedMemorySize, CONV_SMEM);

    prep_weights_kernel<<<512, 256>>>(W_ih, b_ih, W_hh, b_hh, WhhT, W0T, WextT, bias);
    gather_kernel<<<B_N * 16 / 256, 256>>>(program_id, shape_id, shape_id_0, shape_id_1,
                                           pid_emb, sid_emb, s_pid, s_sid, s_sid0, s_sid1);
    conv_fused_kernel<<<B_N, 256, CONV_SMEM>>>(obs, conv1_w, conv1_b, conv2_w, conv2_b, obs_e);
    gemm_xpre_kernel<<<dim3(8, B_N / 64), 256>>>(obs_e, W0T, bias, xpre);

    dim3 sgrid(4, B_N / 64);
    // step0: h=c=0, samp=0, aid=0
    lstm_step_kernel<<<sgrid, 256>>>(xpre, nullptr, nullptr, nullptr, WhhT, WextT, addr_emb, 0, h0, c0);
    head_linear_kernel<<<B_N / 8, 256>>>(h0, pid_ext_w, pid_ext_b, 3, 0, out);
    // branch A
    lstm_step_kernel<<<sgrid, 256>>>(xpre, h0, c0, s_pid, WhhT, WextT, addr_emb, 1, h1, c1);
    head_linear_kernel<<<B_N / 8, 256>>>(h1, sid_ext_w, sid_ext_b, 2, 3, out);
    lstm_step_kernel<<<sgrid, 256>>>(xpre, h1, c1, s_sid, WhhT, WextT, addr_emb, 4, h2, c2);
    head_rp_kernel<<<B_N / 8, 256>>>(h2, rp_ext_w, rp_ext_b, eps_rp, 5, out, nullptr);
    // branch B
    lstm_step_kernel<<<sgrid, 256>>>(xpre, h0, c0, s_pid, WhhT, WextT, addr_emb, 2, h1b, c1b);
    head_linear_kernel<<<B_N / 8, 256>>>(h1b, sid_ext_w, sid_ext_b, 2, 7, out);
    lstm_step_kernel<<<sgrid, 256>>>(xpre, h1b, c1b, s_sid0, WhhT, WextT, addr_emb, 3, h2b, c2b);
    head_linear_kernel<<<B_N / 8, 256>>>(h2b, sid_ext_w, sid_ext_b, 2, 9, out);
    lstm_step_kernel<<<sgrid, 256>>>(xpre, h2b, c2b, s_sid1, WhhT, WextT, addr_emb, 5, h3b, c3b);
    head_rp_kernel<<<B_N / 8, 256>>>(h3b, rp_ext_w, rp_ext_b, eps_rp0, 11, out, rp0);
    // MLP on rp0
    mlp1_kernel<<<(B_N * 100 + 255) / 256, 256>>>(rp0, mlp_w1, mlp_b1, z1);
    mlp2_kernel<<<B_N / 8, 128>>>(z1, mlp_w2, mlp_b2, z2);
    mlp3_kernel<<<B_N * 16 / 256, 256>>>(z2, mlp_w3, mlp_b3, rp0emb);
    // final step + head
    lstm_step_kernel<<<sgrid, 256>>>(xpre, h3b, c3b, rp0emb, WhhT, WextT, addr_emb, 6, h4b, c4b);
    head_rp_kernel<<<B_N / 8, 256>>>(h4b, rp_ext_w, rp_ext_b, eps_rp1, 13, out, nullptr);
}